// round 9
// baseline (speedup 1.0000x reference)
#include <cuda_runtime.h>
#include <stdint.h>

#define NBINS     100
#define THREADS   256         // minmax block size
#define THREADS_H 1024        // hist block size (2 blocks/SM -> 64 warps = full occ)
#define GRID      1184        // minmax: 148 SMs * 8 blocks
#define GRID_H    296         // hist: 148 SMs * 2 blocks

__device__ float        g_bmin[GRID];
__device__ float        g_bmax[GRID];
__device__ unsigned int g_hist[NBINS];   // zero-init at load; last block restores zero
__device__ unsigned int g_done;          // ticket counter; restored to 0 each run

// Forward sweep: finishes with the array TAIL resident in L2 (hist reads it first).
__global__ void __launch_bounds__(THREADS) minmax_kernel(const float* __restrict__ x, int n) {
    int n4 = n >> 2;
    const float4* __restrict__ x4 = (const float4*)x;

    float mn =  3.402823466e+38f;
    float mx = -3.402823466e+38f;

    const int stride = GRID * THREADS;
    int i = blockIdx.x * THREADS + threadIdx.x;

    for (; i + 3 * stride < n4; i += 4 * stride) {
        float4 v0 = x4[i];
        float4 v1 = x4[i + stride];
        float4 v2 = x4[i + 2 * stride];
        float4 v3 = x4[i + 3 * stride];
        mn = fminf(mn, fminf(fminf(v0.x, v0.y), fminf(v0.z, v0.w)));
        mx = fmaxf(mx, fmaxf(fmaxf(v0.x, v0.y), fmaxf(v0.z, v0.w)));
        mn = fminf(mn, fminf(fminf(v1.x, v1.y), fminf(v1.z, v1.w)));
        mx = fmaxf(mx, fmaxf(fmaxf(v1.x, v1.y), fmaxf(v1.z, v1.w)));
        mn = fminf(mn, fminf(fminf(v2.x, v2.y), fminf(v2.z, v2.w)));
        mx = fmaxf(mx, fmaxf(fmaxf(v2.x, v2.y), fmaxf(v2.z, v2.w)));
        mn = fminf(mn, fminf(fminf(v3.x, v3.y), fminf(v3.z, v3.w)));
        mx = fmaxf(mx, fmaxf(fmaxf(v3.x, v3.y), fmaxf(v3.z, v3.w)));
    }
    for (; i < n4; i += stride) {
        float4 v = x4[i];
        mn = fminf(mn, fminf(fminf(v.x, v.y), fminf(v.z, v.w)));
        mx = fmaxf(mx, fmaxf(fmaxf(v.x, v.y), fmaxf(v.z, v.w)));
    }
    if (blockIdx.x == 0) {
        int base = n4 << 2;
        for (int j = base + threadIdx.x; j < n; j += THREADS) {
            float v = x[j];
            mn = fminf(mn, v);
            mx = fmaxf(mx, v);
        }
    }

    #pragma unroll
    for (int o = 16; o > 0; o >>= 1) {
        mn = fminf(mn, __shfl_xor_sync(0xFFFFFFFFu, mn, o));
        mx = fmaxf(mx, __shfl_xor_sync(0xFFFFFFFFu, mx, o));
    }
    __shared__ float smn[THREADS / 32];
    __shared__ float smx[THREADS / 32];
    int wid = threadIdx.x >> 5;
    int lid = threadIdx.x & 31;
    if (lid == 0) { smn[wid] = mn; smx[wid] = mx; }
    __syncthreads();
    if (wid == 0) {
        mn = (lid < THREADS / 32) ? smn[lid] :  3.402823466e+38f;
        mx = (lid < THREADS / 32) ? smx[lid] : -3.402823466e+38f;
        #pragma unroll
        for (int o = 4; o > 0; o >>= 1) {
            mn = fminf(mn, __shfl_xor_sync(0xFFFFFFFFu, mn, o));
            mx = fmaxf(mx, __shfl_xor_sync(0xFFFFFFFFu, mx, o));
        }
        if (lid == 0) {
            g_bmin[blockIdx.x] = mn;
            g_bmax[blockIdx.x] = mx;
        }
    }
}

// hmin is the true data min, so (x - hmin) >= 0 exactly; only the upper clamp
// is needed. Keep FADD+FMUL (not fused) to match reference rounding exactly.
__device__ __forceinline__ int bin_of(float x, float hmin, float scale) {
    float d = (x - hmin) * scale;
    int b = __float2int_rd(d);
    return min(b, NBINS - 1);
}

// Conflict-free shared atomics: 32 bank-aligned replicas, cnt[bin*32 + lane].
// Every lane always hits bank==lane -> max bank load = 1 for ANY data.
// Cross-warp same-copy races resolved by atomicAdd (no conflicts, just pipe).
__global__ void __launch_bounds__(THREADS_H) hist_kernel(const float* __restrict__ x, int n,
                                                         float* __restrict__ out) {
    __shared__ unsigned int cnt[NBINS * 32];   // 12.8 KB
    __shared__ float s_hmin, s_hmax;

    const int tid  = threadIdx.x;
    const int lane = tid & 31;

    // ---- zero replicas ----
    for (int j = tid; j < NBINS * 32; j += THREADS_H) cnt[j] = 0u;

    // ---- re-reduce per-block min/max from L2 ----
    {
        float mn =  3.402823466e+38f;
        float mx = -3.402823466e+38f;
        for (int j = tid; j < GRID; j += THREADS_H) {
            mn = fminf(mn, g_bmin[j]);
            mx = fmaxf(mx, g_bmax[j]);
        }
        #pragma unroll
        for (int o = 16; o > 0; o >>= 1) {
            mn = fminf(mn, __shfl_xor_sync(0xFFFFFFFFu, mn, o));
            mx = fmaxf(mx, __shfl_xor_sync(0xFFFFFFFFu, mx, o));
        }
        __shared__ float rmn[THREADS_H / 32], rmx[THREADS_H / 32];
        int wid = tid >> 5;
        if (lane == 0) { rmn[wid] = mn; rmx[wid] = mx; }
        __syncthreads();
        if (tid == 0) {
            float fmn = rmn[0], fmx = rmx[0];
            #pragma unroll
            for (int w = 1; w < THREADS_H / 32; w++) {
                fmn = fminf(fmn, rmn[w]);
                fmx = fmaxf(fmx, rmx[w]);
            }
            if (fmx == fmn) fmx = fmn + 1.0f;   // degenerate-range guard
            s_hmin = fmn;
            s_hmax = fmx;
        }
        __syncthreads();
    }

    const float hmin  = s_hmin;
    const float scale = (float)NBINS / (s_hmax - hmin);

    unsigned int* my = cnt + lane;              // lane-private bank column

    int n4 = n >> 2;
    const float4* __restrict__ x4 = (const float4*)x;
    const int stride = GRID_H * THREADS_H;

    // descending grid-stride, 4 independent float4 loads in flight
    int i = (n4 - 1) - (int)(blockIdx.x * THREADS_H + tid);

    for (; i - 3 * stride >= 0; i -= 4 * stride) {
        float4 v0 = x4[i];
        float4 v1 = x4[i - stride];
        float4 v2 = x4[i - 2 * stride];
        float4 v3 = x4[i - 3 * stride];
        atomicAdd(&my[bin_of(v0.x, hmin, scale) * 32], 1u);
        atomicAdd(&my[bin_of(v0.y, hmin, scale) * 32], 1u);
        atomicAdd(&my[bin_of(v0.z, hmin, scale) * 32], 1u);
        atomicAdd(&my[bin_of(v0.w, hmin, scale) * 32], 1u);
        atomicAdd(&my[bin_of(v1.x, hmin, scale) * 32], 1u);
        atomicAdd(&my[bin_of(v1.y, hmin, scale) * 32], 1u);
        atomicAdd(&my[bin_of(v1.z, hmin, scale) * 32], 1u);
        atomicAdd(&my[bin_of(v1.w, hmin, scale) * 32], 1u);
        atomicAdd(&my[bin_of(v2.x, hmin, scale) * 32], 1u);
        atomicAdd(&my[bin_of(v2.y, hmin, scale) * 32], 1u);
        atomicAdd(&my[bin_of(v2.z, hmin, scale) * 32], 1u);
        atomicAdd(&my[bin_of(v2.w, hmin, scale) * 32], 1u);
        atomicAdd(&my[bin_of(v3.x, hmin, scale) * 32], 1u);
        atomicAdd(&my[bin_of(v3.y, hmin, scale) * 32], 1u);
        atomicAdd(&my[bin_of(v3.z, hmin, scale) * 32], 1u);
        atomicAdd(&my[bin_of(v3.w, hmin, scale) * 32], 1u);
    }
    for (; i >= 0; i -= stride) {
        float4 v = x4[i];
        atomicAdd(&my[bin_of(v.x, hmin, scale) * 32], 1u);
        atomicAdd(&my[bin_of(v.y, hmin, scale) * 32], 1u);
        atomicAdd(&my[bin_of(v.z, hmin, scale) * 32], 1u);
        atomicAdd(&my[bin_of(v.w, hmin, scale) * 32], 1u);
    }
    if (blockIdx.x == 0) {
        int base = n4 << 2;
        for (int j = base + tid; j < n; j += THREADS_H) {
            atomicAdd(&my[bin_of(x[j], hmin, scale) * 32], 1u);
        }
    }
    __syncthreads();

    // ---- reduce 32 replicas: warp w handles bins w, w+32, ... (bank=lane reads) ----
    {
        int wid = tid >> 5;
        for (int b = wid; b < NBINS; b += THREADS_H / 32) {
            unsigned int s = cnt[b * 32 + lane];
            #pragma unroll
            for (int o = 16; o > 0; o >>= 1)
                s += __shfl_xor_sync(0xFFFFFFFFu, s, o);
            if (lane == 0 && s) atomicAdd(&g_hist[b], s);
        }
    }

    // ---- fused finalize: last block converts g_hist -> out, restores zeros ----
    __threadfence();
    __syncthreads();
    __shared__ unsigned int s_ticket;
    if (tid == 0) s_ticket = atomicAdd(&g_done, 1u);
    __syncthreads();
    if (s_ticket == GRID_H - 1) {
        __threadfence();
        for (int b = tid; b < NBINS; b += THREADS_H) {
            out[b] = (float)g_hist[b];
            g_hist[b] = 0u;
        }
        if (tid == 0) g_done = 0u;
    }
}

extern "C" void kernel_launch(void* const* d_in, const int* in_sizes, int n_in,
                              void* d_out, int out_size) {
    const float* x = (const float*)d_in[0];
    int n = in_sizes[0];
    float* out = (float*)d_out;

    minmax_kernel<<<GRID, THREADS>>>(x, n);
    hist_kernel<<<GRID_H, THREADS_H>>>(x, n, out);
}

// round 10
// speedup vs baseline: 1.0506x; 1.0506x over previous
#include <cuda_runtime.h>
#include <stdint.h>

#define NBINS     100
#define THREADS   256         // minmax block size
#define THREADS_H 512         // hist block size (4 blocks/SM -> 64 warps, 4 tables/SM)
#define GRID      1184        // minmax: 148 SMs * 8 blocks
#define GRID_H    592         // hist: 148 SMs * 4 blocks (40KB smem each)
#define TBL       (NBINS * NBINS)   // 10000-entry 2D pair table

__device__ float        g_bmin[GRID];
__device__ float        g_bmax[GRID];
__device__ unsigned int g_hist[NBINS];   // zero-init at load; last block restores zero
__device__ unsigned int g_done;          // ticket counter; restored to 0 each run

// Forward sweep: finishes with the array TAIL resident in L2; reverse hist +
// next-replay forward minmax both collect the carryover.
__global__ void __launch_bounds__(THREADS) minmax_kernel(const float* __restrict__ x, int n) {
    int n4 = n >> 2;
    const float4* __restrict__ x4 = (const float4*)x;

    float mn =  3.402823466e+38f;
    float mx = -3.402823466e+38f;

    const int stride = GRID * THREADS;
    int i = blockIdx.x * THREADS + threadIdx.x;

    // 8 independent LDG.128 in flight per warp
    for (; i + 7 * stride < n4; i += 8 * stride) {
        float4 v0 = x4[i];
        float4 v1 = x4[i + stride];
        float4 v2 = x4[i + 2 * stride];
        float4 v3 = x4[i + 3 * stride];
        float4 v4 = x4[i + 4 * stride];
        float4 v5 = x4[i + 5 * stride];
        float4 v6 = x4[i + 6 * stride];
        float4 v7 = x4[i + 7 * stride];
        mn = fminf(mn, fminf(fminf(v0.x, v0.y), fminf(v0.z, v0.w)));
        mx = fmaxf(mx, fmaxf(fmaxf(v0.x, v0.y), fmaxf(v0.z, v0.w)));
        mn = fminf(mn, fminf(fminf(v1.x, v1.y), fminf(v1.z, v1.w)));
        mx = fmaxf(mx, fmaxf(fmaxf(v1.x, v1.y), fmaxf(v1.z, v1.w)));
        mn = fminf(mn, fminf(fminf(v2.x, v2.y), fminf(v2.z, v2.w)));
        mx = fmaxf(mx, fmaxf(fmaxf(v2.x, v2.y), fmaxf(v2.z, v2.w)));
        mn = fminf(mn, fminf(fminf(v3.x, v3.y), fminf(v3.z, v3.w)));
        mx = fmaxf(mx, fmaxf(fmaxf(v3.x, v3.y), fmaxf(v3.z, v3.w)));
        mn = fminf(mn, fminf(fminf(v4.x, v4.y), fminf(v4.z, v4.w)));
        mx = fmaxf(mx, fmaxf(fmaxf(v4.x, v4.y), fmaxf(v4.z, v4.w)));
        mn = fminf(mn, fminf(fminf(v5.x, v5.y), fminf(v5.z, v5.w)));
        mx = fmaxf(mx, fmaxf(fmaxf(v5.x, v5.y), fmaxf(v5.z, v5.w)));
        mn = fminf(mn, fminf(fminf(v6.x, v6.y), fminf(v6.z, v6.w)));
        mx = fmaxf(mx, fmaxf(fmaxf(v6.x, v6.y), fmaxf(v6.z, v6.w)));
        mn = fminf(mn, fminf(fminf(v7.x, v7.y), fminf(v7.z, v7.w)));
        mx = fmaxf(mx, fmaxf(fmaxf(v7.x, v7.y), fmaxf(v7.z, v7.w)));
    }
    for (; i < n4; i += stride) {
        float4 v = x4[i];
        mn = fminf(mn, fminf(fminf(v.x, v.y), fminf(v.z, v.w)));
        mx = fmaxf(mx, fmaxf(fmaxf(v.x, v.y), fmaxf(v.z, v.w)));
    }
    if (blockIdx.x == 0) {
        int base = n4 << 2;
        for (int j = base + threadIdx.x; j < n; j += THREADS) {
            float v = x[j];
            mn = fminf(mn, v);
            mx = fmaxf(mx, v);
        }
    }

    #pragma unroll
    for (int o = 16; o > 0; o >>= 1) {
        mn = fminf(mn, __shfl_xor_sync(0xFFFFFFFFu, mn, o));
        mx = fmaxf(mx, __shfl_xor_sync(0xFFFFFFFFu, mx, o));
    }
    __shared__ float smn[THREADS / 32];
    __shared__ float smx[THREADS / 32];
    int wid = threadIdx.x >> 5;
    int lid = threadIdx.x & 31;
    if (lid == 0) { smn[wid] = mn; smx[wid] = mx; }
    __syncthreads();
    if (wid == 0) {
        mn = (lid < THREADS / 32) ? smn[lid] :  3.402823466e+38f;
        mx = (lid < THREADS / 32) ? smx[lid] : -3.402823466e+38f;
        #pragma unroll
        for (int o = 4; o > 0; o >>= 1) {
            mn = fminf(mn, __shfl_xor_sync(0xFFFFFFFFu, mn, o));
            mx = fmaxf(mx, __shfl_xor_sync(0xFFFFFFFFu, mx, o));
        }
        if (lid == 0) {
            g_bmin[blockIdx.x] = mn;
            g_bmax[blockIdx.x] = mx;
        }
    }
}

// hmin is the true data min, so (x - hmin) >= 0 exactly; only the upper clamp
// is needed. Keep FADD+FMUL (not fused) to match reference rounding exactly.
__device__ __forceinline__ int bin_of(float x, float hmin, float scale) {
    float d = (x - hmin) * scale;
    int b = __float2int_rd(d);
    return min(b, NBINS - 1);
}

// Pair-binning, 4 blocks/SM: one shared atomic per TWO elements into a private
// 100x100 table; only 16 warps share each table (vs 64 in R8) -> 4x lower
// same-address contention at the smem atomic ALU. 1D hist = row+col marginals.
__global__ void __launch_bounds__(THREADS_H, 4) hist_kernel(const float* __restrict__ x, int n,
                                                            float* __restrict__ out) {
    __shared__ unsigned int t2[TBL];        // 40 KB pair table
    __shared__ float s_hmin, s_hmax;

    const int tid = threadIdx.x;

    // ---- zero pair table ----
    for (int j = tid; j < TBL; j += THREADS_H) t2[j] = 0u;

    // ---- re-reduce per-block min/max from L2 ----
    {
        float mn =  3.402823466e+38f;
        float mx = -3.402823466e+38f;
        for (int j = tid; j < GRID; j += THREADS_H) {
            mn = fminf(mn, g_bmin[j]);
            mx = fmaxf(mx, g_bmax[j]);
        }
        #pragma unroll
        for (int o = 16; o > 0; o >>= 1) {
            mn = fminf(mn, __shfl_xor_sync(0xFFFFFFFFu, mn, o));
            mx = fmaxf(mx, __shfl_xor_sync(0xFFFFFFFFu, mx, o));
        }
        __shared__ float rmn[THREADS_H / 32], rmx[THREADS_H / 32];
        int wid = tid >> 5;
        int lid = tid & 31;
        if (lid == 0) { rmn[wid] = mn; rmx[wid] = mx; }
        __syncthreads();
        if (tid == 0) {
            float fmn = rmn[0], fmx = rmx[0];
            #pragma unroll
            for (int w = 1; w < THREADS_H / 32; w++) {
                fmn = fminf(fmn, rmn[w]);
                fmx = fmaxf(fmx, rmx[w]);
            }
            if (fmx == fmn) fmx = fmn + 1.0f;   // degenerate-range guard
            s_hmin = fmn;
            s_hmax = fmx;
        }
        __syncthreads();
    }

    const float hmin  = s_hmin;
    const float scale = (float)NBINS / (s_hmax - hmin);

    int n4 = n >> 2;
    const float4* __restrict__ x4 = (const float4*)x;
    const int stride = GRID_H * THREADS_H;

    // descending grid-stride, 4 independent float4 loads in flight
    int i = (n4 - 1) - (int)(blockIdx.x * THREADS_H + tid);

    for (; i - 3 * stride >= 0; i -= 4 * stride) {
        float4 v0 = x4[i];
        float4 v1 = x4[i - stride];
        float4 v2 = x4[i - 2 * stride];
        float4 v3 = x4[i - 3 * stride];
        atomicAdd(&t2[bin_of(v0.x, hmin, scale) * NBINS + bin_of(v0.y, hmin, scale)], 1u);
        atomicAdd(&t2[bin_of(v0.z, hmin, scale) * NBINS + bin_of(v0.w, hmin, scale)], 1u);
        atomicAdd(&t2[bin_of(v1.x, hmin, scale) * NBINS + bin_of(v1.y, hmin, scale)], 1u);
        atomicAdd(&t2[bin_of(v1.z, hmin, scale) * NBINS + bin_of(v1.w, hmin, scale)], 1u);
        atomicAdd(&t2[bin_of(v2.x, hmin, scale) * NBINS + bin_of(v2.y, hmin, scale)], 1u);
        atomicAdd(&t2[bin_of(v2.z, hmin, scale) * NBINS + bin_of(v2.w, hmin, scale)], 1u);
        atomicAdd(&t2[bin_of(v3.x, hmin, scale) * NBINS + bin_of(v3.y, hmin, scale)], 1u);
        atomicAdd(&t2[bin_of(v3.z, hmin, scale) * NBINS + bin_of(v3.w, hmin, scale)], 1u);
    }
    for (; i >= 0; i -= stride) {
        float4 v = x4[i];
        atomicAdd(&t2[bin_of(v.x, hmin, scale) * NBINS + bin_of(v.y, hmin, scale)], 1u);
        atomicAdd(&t2[bin_of(v.z, hmin, scale) * NBINS + bin_of(v.w, hmin, scale)], 1u);
    }
    if (blockIdx.x == 0) {
        // scalar tail (n % 4): straight to global bins (before ticket/finalize)
        int base = n4 << 2;
        for (int j = base + tid; j < n; j += THREADS_H) {
            atomicAdd(&g_hist[bin_of(x[j], hmin, scale)], 1u);
        }
    }
    __syncthreads();

    // ---- marginals: one global atomic per (block, bin) for rows and cols ----
    for (int b1 = tid; b1 < NBINS; b1 += THREADS_H) {
        unsigned int s = 0;
        #pragma unroll 4
        for (int b2 = 0; b2 < NBINS; b2++) s += t2[b1 * NBINS + b2];
        if (s) atomicAdd(&g_hist[b1], s);
    }
    for (int b2 = tid; b2 < NBINS; b2 += THREADS_H) {
        unsigned int s = 0;
        #pragma unroll 4
        for (int b1 = 0; b1 < NBINS; b1++) s += t2[b1 * NBINS + b2];
        if (s) atomicAdd(&g_hist[b2], s);
    }

    // ---- fused finalize: last block converts g_hist -> out, restores zeros ----
    __threadfence();
    __syncthreads();
    __shared__ unsigned int s_ticket;
    if (tid == 0) s_ticket = atomicAdd(&g_done, 1u);
    __syncthreads();
    if (s_ticket == GRID_H - 1) {
        __threadfence();
        for (int b = tid; b < NBINS; b += THREADS_H) {
            out[b] = (float)g_hist[b];
            g_hist[b] = 0u;
        }
        if (tid == 0) g_done = 0u;
    }
}

extern "C" void kernel_launch(void* const* d_in, const int* in_sizes, int n_in,
                              void* d_out, int out_size) {
    const float* x = (const float*)d_in[0];
    int n = in_sizes[0];
    float* out = (float*)d_out;

    minmax_kernel<<<GRID, THREADS>>>(x, n);
    hist_kernel<<<GRID_H, THREADS_H>>>(x, n, out);
}

// round 11
// speedup vs baseline: 1.1122x; 1.0586x over previous
#include <cuda_runtime.h>
#include <stdint.h>

#define NBINS     100
#define THREADS_H 1024        // 2 blocks/SM -> 64 warps = full occ
#define GRID_H    296         // 148 SMs * 2 blocks, all co-resident (safe grid sync)
#define TBL       (NBINS * NBINS)   // 10000-entry 2D pair table

__device__ float                 g_bmin[GRID_H];
__device__ float                 g_bmax[GRID_H];
__device__ unsigned int          g_hist[NBINS];  // zero-init; finalize restores zero
__device__ unsigned int          g_done;         // finalize ticket; restored to 0
__device__ volatile unsigned int g_sync1;        // phase-1 barrier; restored to 0

// hmin is the true data min, so (x - hmin) >= 0 exactly; only the upper clamp
// is needed. Keep FADD+FMUL (not fused) to match reference rounding exactly.
__device__ __forceinline__ int bin_of(float x, float hmin, float scale) {
    float d = (x - hmin) * scale;
    int b = __float2int_rd(d);
    return min(b, NBINS - 1);
}

// Fused persistent kernel:
//   phase 1: forward min/max sweep (leaves array TAIL hot in L2)
//   grid barrier (all 296 blocks co-resident by construction)
//   phase 2: reverse pair-binning hist (reads hot tail first; leaves HEAD hot
//            for the next graph replay's phase 1)
__global__ void __launch_bounds__(THREADS_H, 2)
fused_kernel(const float* __restrict__ x, int n, float* __restrict__ out) {
    __shared__ unsigned int t2[TBL];        // 40 KB pair table
    __shared__ float s_hmin, s_hmax;

    const int tid = threadIdx.x;
    int n4 = n >> 2;
    const float4* __restrict__ x4 = (const float4*)x;
    const int stride = GRID_H * THREADS_H;

    // ================= phase 1: min/max (forward) =================
    {
        float mn =  3.402823466e+38f;
        float mx = -3.402823466e+38f;

        int i = blockIdx.x * THREADS_H + tid;
        for (; i + 3 * stride < n4; i += 4 * stride) {
            float4 v0 = x4[i];
            float4 v1 = x4[i + stride];
            float4 v2 = x4[i + 2 * stride];
            float4 v3 = x4[i + 3 * stride];
            mn = fminf(mn, fminf(fminf(v0.x, v0.y), fminf(v0.z, v0.w)));
            mx = fmaxf(mx, fmaxf(fmaxf(v0.x, v0.y), fmaxf(v0.z, v0.w)));
            mn = fminf(mn, fminf(fminf(v1.x, v1.y), fminf(v1.z, v1.w)));
            mx = fmaxf(mx, fmaxf(fmaxf(v1.x, v1.y), fmaxf(v1.z, v1.w)));
            mn = fminf(mn, fminf(fminf(v2.x, v2.y), fminf(v2.z, v2.w)));
            mx = fmaxf(mx, fmaxf(fmaxf(v2.x, v2.y), fmaxf(v2.z, v2.w)));
            mn = fminf(mn, fminf(fminf(v3.x, v3.y), fminf(v3.z, v3.w)));
            mx = fmaxf(mx, fmaxf(fmaxf(v3.x, v3.y), fmaxf(v3.z, v3.w)));
        }
        for (; i < n4; i += stride) {
            float4 v = x4[i];
            mn = fminf(mn, fminf(fminf(v.x, v.y), fminf(v.z, v.w)));
            mx = fmaxf(mx, fmaxf(fmaxf(v.x, v.y), fmaxf(v.z, v.w)));
        }
        if (blockIdx.x == 0) {
            int base = n4 << 2;
            for (int j = base + tid; j < n; j += THREADS_H) {
                float v = x[j];
                mn = fminf(mn, v);
                mx = fmaxf(mx, v);
            }
        }

        #pragma unroll
        for (int o = 16; o > 0; o >>= 1) {
            mn = fminf(mn, __shfl_xor_sync(0xFFFFFFFFu, mn, o));
            mx = fmaxf(mx, __shfl_xor_sync(0xFFFFFFFFu, mx, o));
        }
        __shared__ float smn[THREADS_H / 32];
        __shared__ float smx[THREADS_H / 32];
        int wid = tid >> 5;
        int lid = tid & 31;
        if (lid == 0) { smn[wid] = mn; smx[wid] = mx; }
        __syncthreads();
        if (tid == 0) {
            float fmn = smn[0], fmx = smx[0];
            #pragma unroll
            for (int w = 1; w < THREADS_H / 32; w++) {
                fmn = fminf(fmn, smn[w]);
                fmx = fmaxf(fmx, smx[w]);
            }
            g_bmin[blockIdx.x] = fmn;
            g_bmax[blockIdx.x] = fmx;
        }
    }

    // ================= grid barrier (all blocks co-resident) =================
    // Zero the pair table while waiting (independent of barrier state).
    __threadfence();                 // publish g_bmin/g_bmax
    __syncthreads();                 // all threads' phase-1 work done
    if (tid == 0) {
        __shared__ unsigned int dummy;  (void)dummy;
        atomicAdd((unsigned int*)&g_sync1, 1u);
    }
    for (int j = tid; j < TBL; j += THREADS_H) t2[j] = 0u;   // overlap with spin
    if (tid == 0) {
        while (g_sync1 < GRID_H) { /* spin */ }
    }
    __syncthreads();                 // release whole block
    __threadfence();                 // acquire other blocks' g_bmin/g_bmax

    // ================= global min/max reduce =================
    {
        float mn =  3.402823466e+38f;
        float mx = -3.402823466e+38f;
        for (int j = tid; j < GRID_H; j += THREADS_H) {
            mn = fminf(mn, g_bmin[j]);
            mx = fmaxf(mx, g_bmax[j]);
        }
        #pragma unroll
        for (int o = 16; o > 0; o >>= 1) {
            mn = fminf(mn, __shfl_xor_sync(0xFFFFFFFFu, mn, o));
            mx = fmaxf(mx, __shfl_xor_sync(0xFFFFFFFFu, mx, o));
        }
        __shared__ float rmn[THREADS_H / 32], rmx[THREADS_H / 32];
        int wid = tid >> 5;
        int lid = tid & 31;
        if (lid == 0) { rmn[wid] = mn; rmx[wid] = mx; }
        __syncthreads();
        if (tid == 0) {
            float fmn = rmn[0], fmx = rmx[0];
            #pragma unroll
            for (int w = 1; w < THREADS_H / 32; w++) {
                fmn = fminf(fmn, rmn[w]);
                fmx = fmaxf(fmx, rmx[w]);
            }
            if (fmx == fmn) fmx = fmn + 1.0f;   // degenerate-range guard
            s_hmin = fmn;
            s_hmax = fmx;
        }
        __syncthreads();
    }

    const float hmin  = s_hmin;
    const float scale = (float)NBINS / (s_hmax - hmin);

    // ================= phase 2: pair-binning hist (reverse) =================
    {
        int i = (n4 - 1) - (int)(blockIdx.x * THREADS_H + tid);

        for (; i - 3 * stride >= 0; i -= 4 * stride) {
            float4 v0 = x4[i];
            float4 v1 = x4[i - stride];
            float4 v2 = x4[i - 2 * stride];
            float4 v3 = x4[i - 3 * stride];
            atomicAdd(&t2[bin_of(v0.x, hmin, scale) * NBINS + bin_of(v0.y, hmin, scale)], 1u);
            atomicAdd(&t2[bin_of(v0.z, hmin, scale) * NBINS + bin_of(v0.w, hmin, scale)], 1u);
            atomicAdd(&t2[bin_of(v1.x, hmin, scale) * NBINS + bin_of(v1.y, hmin, scale)], 1u);
            atomicAdd(&t2[bin_of(v1.z, hmin, scale) * NBINS + bin_of(v1.w, hmin, scale)], 1u);
            atomicAdd(&t2[bin_of(v2.x, hmin, scale) * NBINS + bin_of(v2.y, hmin, scale)], 1u);
            atomicAdd(&t2[bin_of(v2.z, hmin, scale) * NBINS + bin_of(v2.w, hmin, scale)], 1u);
            atomicAdd(&t2[bin_of(v3.x, hmin, scale) * NBINS + bin_of(v3.y, hmin, scale)], 1u);
            atomicAdd(&t2[bin_of(v3.z, hmin, scale) * NBINS + bin_of(v3.w, hmin, scale)], 1u);
        }
        for (; i >= 0; i -= stride) {
            float4 v = x4[i];
            atomicAdd(&t2[bin_of(v.x, hmin, scale) * NBINS + bin_of(v.y, hmin, scale)], 1u);
            atomicAdd(&t2[bin_of(v.z, hmin, scale) * NBINS + bin_of(v.w, hmin, scale)], 1u);
        }
        if (blockIdx.x == 0) {
            int base = n4 << 2;
            for (int j = base + tid; j < n; j += THREADS_H) {
                atomicAdd(&g_hist[bin_of(x[j], hmin, scale)], 1u);
            }
        }
        __syncthreads();
    }

    // ---- marginals: one global atomic per (block, bin) for rows and cols ----
    for (int b1 = tid; b1 < NBINS; b1 += THREADS_H) {
        unsigned int s = 0;
        #pragma unroll 4
        for (int b2 = 0; b2 < NBINS; b2++) s += t2[b1 * NBINS + b2];
        if (s) atomicAdd(&g_hist[b1], s);
    }
    for (int b2 = tid; b2 < NBINS; b2 += THREADS_H) {
        unsigned int s = 0;
        #pragma unroll 4
        for (int b1 = 0; b1 < NBINS; b1++) s += t2[b1 * NBINS + b2];
        if (s) atomicAdd(&g_hist[b2], s);
    }

    // ---- finalize: last block converts g_hist -> out, restores global state ----
    __threadfence();
    __syncthreads();
    __shared__ unsigned int s_ticket;
    if (tid == 0) s_ticket = atomicAdd(&g_done, 1u);
    __syncthreads();
    if (s_ticket == GRID_H - 1) {
        __threadfence();
        for (int b = tid; b < NBINS; b += THREADS_H) {
            out[b] = (float)g_hist[b];
            g_hist[b] = 0u;
        }
        if (tid == 0) {
            g_done  = 0u;
            g_sync1 = 0u;   // safe: every block already passed the barrier
        }
    }
}

extern "C" void kernel_launch(void* const* d_in, const int* in_sizes, int n_in,
                              void* d_out, int out_size) {
    const float* x = (const float*)d_in[0];
    int n = in_sizes[0];
    float* out = (float*)d_out;

    fused_kernel<<<GRID_H, THREADS_H>>>(x, n, out);
}